// round 2
// baseline (speedup 1.0000x reference)
#include <cuda_runtime.h>
#include <math.h>

#define B  64
#define T  512
#define H  256
#define BT (B*T)

// ---------------- scratch (device globals: no allocation allowed) ----------------
__device__ float g_qW[B*H];                 // b1 + q@(W1_1+W1_2)
__device__ float g_att[BT];                 // att scores -> softmax g (in place)
__device__ float g_preR[BT*H];              // f@Wr + br
__device__ float g_preH[BT*H];              // f@Wh + bh
__device__ float g_eout[BT*H];              // GRU outputs (valid rows only)
__device__ float g_qs[B];                   // bs + q@Ws[:H]
__device__ float g_qe[B];                   // be + q@We[:H]

__device__ __forceinline__ float sigf(float x) { return 1.0f / (1.0f + expf(-x)); }

// ---------------- K1: qW[b,n] = b1[n] + sum_k q[b,k]*(W1[H+k,n]+W1[2H+k,n]) ------
__global__ void k_qw(const float* __restrict__ q, const float* __restrict__ W1,
                     const float* __restrict__ b1) {
    int b = blockIdx.x, n = threadIdx.x;
    __shared__ float qs[H];
    qs[n] = q[b*H + n];
    __syncthreads();
    float a0 = 0.f, a1 = 0.f, a2 = 0.f, a3 = 0.f;
    const float* wa = W1 + 1*H*H + n;
    const float* wb = W1 + 2*H*H + n;
    #pragma unroll 4
    for (int k = 0; k < H; k += 4) {
        a0 += qs[k+0] * (wa[(k+0)*H] + wb[(k+0)*H]);
        a1 += qs[k+1] * (wa[(k+1)*H] + wb[(k+1)*H]);
        a2 += qs[k+2] * (wa[(k+2)*H] + wb[(k+2)*H]);
        a3 += qs[k+3] * (wa[(k+3)*H] + wb[(k+3)*H]);
    }
    g_qW[b*H + n] = b1[n] + a0 + a1 + a2 + a3;
}

// ---------------- K1b: qs[b] = bs + q[b]@Ws[:H];  qe[b] = be + q[b]@We[:H] -------
__global__ void k_qsqe(const float* __restrict__ q, const float* __restrict__ Ws,
                       const float* __restrict__ bs_, const float* __restrict__ We,
                       const float* __restrict__ be_) {
    int b = threadIdx.x;  // 64 threads
    float s = bs_[0], e = be_[0];
    #pragma unroll 4
    for (int k = 0; k < H; k++) {
        float qv = q[b*H + k];
        s += qv * Ws[k];
        e += qv * We[k];
    }
    g_qs[b] = s;
    g_qe[b] = e;
}

// ---------------- K2: attention scores --------------------------------------------
// att[row] = b2 + sum_n tanh( qW[b,n] + sum_k A[row,k]*Wc[k,n] ) * W2[n]
// A segments (K=768): f, f*q, |f-q|.  Tile 64 rows x 256 cols, 8x8 microtile.
__launch_bounds__(256, 2)
__global__ void k_att(const float* __restrict__ f, const float* __restrict__ q,
                      const float* __restrict__ W1, const float* __restrict__ W2,
                      const float* __restrict__ b2) {
    __shared__ __align__(16) float As[32*68];    // [k][row], padded stride 68
    __shared__ __align__(16) float Bs[32*256];   // [k][n]
    __shared__ float qs[H], qWs[H], W2s[H];

    int tid  = threadIdx.x;
    int tile = blockIdx.x;            // 0..511
    int row0 = tile * 64;
    int b    = tile >> 3;             // 8 tiles per batch (512 rows/batch)

    qs[tid]  = q[b*H + tid];
    qWs[tid] = g_qW[b*H + tid];
    W2s[tid] = W2[tid];

    int ri = tid >> 5;                // 0..7  (row group of 8)
    int ci = tid & 31;                // 0..31 (col group of 8)

    float acc[8][8];
    #pragma unroll
    for (int r = 0; r < 8; r++)
        #pragma unroll
        for (int c = 0; c < 8; c++) acc[r][c] = 0.0f;

    for (int seg = 0; seg < 3; seg++) {
        const float* wA;
        const float* wB;
        bool two;
        if (seg == 0)      { wA = W1;           wB = W1;           two = false; }
        else if (seg == 1) { wA = W1 + 3*H*H;   wB = W1 + 4*H*H;   two = true;  }
        else               { wA = W1 + 5*H*H;   wB = W1 + 6*H*H;   two = true;  }

        for (int kt = 0; kt < 8; kt++) {
            __syncthreads();
            // A tile: 64 rows x 32 k, transformed on the fly, stored [k][row]
            #pragma unroll
            for (int i = 0; i < 2; i++) {
                int f4 = tid + i*256;
                int rr = f4 >> 3, k4 = f4 & 7;
                float4 v = *(const float4*)(f + (size_t)(row0+rr)*H + kt*32 + k4*4);
                float a0, a1, a2, a3;
                if (seg == 0) { a0 = v.x; a1 = v.y; a2 = v.z; a3 = v.w; }
                else {
                    float q0 = qs[kt*32 + k4*4 + 0];
                    float q1 = qs[kt*32 + k4*4 + 1];
                    float q2 = qs[kt*32 + k4*4 + 2];
                    float q3 = qs[kt*32 + k4*4 + 3];
                    if (seg == 1) { a0 = v.x*q0; a1 = v.y*q1; a2 = v.z*q2; a3 = v.w*q3; }
                    else { a0 = fabsf(v.x-q0); a1 = fabsf(v.y-q1); a2 = fabsf(v.z-q2); a3 = fabsf(v.w-q3); }
                }
                As[(k4*4+0)*68 + rr] = a0;
                As[(k4*4+1)*68 + rr] = a1;
                As[(k4*4+2)*68 + rr] = a2;
                As[(k4*4+3)*68 + rr] = a3;
            }
            // B tile: 32 k x 256 n (combine the two W1 blocks for seg 1/2)
            #pragma unroll
            for (int i = 0; i < 8; i++) {
                int f4 = tid + i*256;
                int kk = f4 >> 6, nn = (f4 & 63) * 4;
                float4 w = *(const float4*)(wA + (size_t)(kt*32+kk)*H + nn);
                if (two) {
                    float4 w2 = *(const float4*)(wB + (size_t)(kt*32+kk)*H + nn);
                    w.x += w2.x; w.y += w2.y; w.z += w2.z; w.w += w2.w;
                }
                *(float4*)(Bs + kk*256 + nn) = w;
            }
            __syncthreads();

            #pragma unroll
            for (int k = 0; k < 32; k++) {
                float4 a0 = *(float4*)(As + k*68 + ri*8);
                float4 a1 = *(float4*)(As + k*68 + ri*8 + 4);
                float4 b0 = *(float4*)(Bs + k*256 + ci*8);
                float4 b1 = *(float4*)(Bs + k*256 + ci*8 + 4);
                float av[8] = {a0.x,a0.y,a0.z,a0.w,a1.x,a1.y,a1.z,a1.w};
                float bv[8] = {b0.x,b0.y,b0.z,b0.w,b1.x,b1.y,b1.z,b1.w};
                #pragma unroll
                for (int r = 0; r < 8; r++)
                    #pragma unroll
                    for (int c = 0; c < 8; c++)
                        acc[r][c] += av[r] * bv[c];
            }
        }
    }

    // epilogue: tanh, dot with W2, reduce over the 32 col groups
    __syncthreads();
    float* part = As;                  // reuse: 64*33 = 2112 <= 2176
    float b2v = b2[0];
    #pragma unroll
    for (int r = 0; r < 8; r++) {
        float p = 0.0f;
        #pragma unroll
        for (int c = 0; c < 8; c++) {
            int n = ci*8 + c;
            p += tanhf(acc[r][c] + qWs[n]) * W2s[n];
        }
        part[(ri*8 + r)*33 + ci] = p;
    }
    __syncthreads();
    if (tid < 64) {
        float s = b2v;
        #pragma unroll 8
        for (int c = 0; c < 32; c++) s += part[tid*33 + c];
        g_att[row0 + tid] = s;
    }
}

// ---------------- K4: softmax over T per batch ------------------------------------
__global__ void k_softmax() {
    int b = blockIdx.x, t = threadIdx.x;  // 512 threads
    __shared__ float red[512];
    float v = g_att[b*T + t];
    red[t] = v;
    __syncthreads();
    for (int s = 256; s > 0; s >>= 1) {
        if (t < s) red[t] = fmaxf(red[t], red[t+s]);
        __syncthreads();
    }
    float mx = red[0];
    __syncthreads();
    float e = expf(v - mx);
    red[t] = e;
    __syncthreads();
    for (int s = 256; s > 0; s >>= 1) {
        if (t < s) red[t] += red[t+s];
        __syncthreads();
    }
    g_att[b*T + t] = e / red[0];
}

// ---------------- K3: preR = f@Wr + br, preH = f@Wh + bh --------------------------
// grid (512, 4): y in {0,1} -> Wr cols [y*128,..); y in {2,3} -> Wh.
__launch_bounds__(256, 2)
__global__ void k_pre(const float* __restrict__ f,
                      const float* __restrict__ Wr, const float* __restrict__ br,
                      const float* __restrict__ Wh, const float* __restrict__ bh) {
    __shared__ __align__(16) float As[32*68];
    __shared__ __align__(16) float Bs[32*128];
    int tid  = threadIdx.x;
    int row0 = blockIdx.x * 64;
    int y    = blockIdx.y;
    const float* W    = (y < 2) ? Wr : Wh;
    const float* bias = (y < 2) ? br : bh;
    float*       outp = (y < 2) ? g_preR : g_preH;
    int n0 = (y & 1) * 128;
    int ri = tid >> 5, ci = tid & 31;     // 8 rows x 4 cols microtile

    float acc[8][4];
    #pragma unroll
    for (int r = 0; r < 8; r++)
        #pragma unroll
        for (int c = 0; c < 4; c++) acc[r][c] = 0.0f;

    for (int kt = 0; kt < 8; kt++) {
        __syncthreads();
        #pragma unroll
        for (int i = 0; i < 2; i++) {
            int f4 = tid + i*256;
            int rr = f4 >> 3, k4 = f4 & 7;
            float4 v = *(const float4*)(f + (size_t)(row0+rr)*H + kt*32 + k4*4);
            As[(k4*4+0)*68 + rr] = v.x;
            As[(k4*4+1)*68 + rr] = v.y;
            As[(k4*4+2)*68 + rr] = v.z;
            As[(k4*4+3)*68 + rr] = v.w;
        }
        #pragma unroll
        for (int i = 0; i < 4; i++) {
            int f4 = tid + i*256;
            int kk = f4 >> 5, nn = (f4 & 31) * 4;
            *(float4*)(Bs + kk*128 + nn) =
                *(const float4*)(W + (size_t)(kt*32+kk)*H + n0 + nn);
        }
        __syncthreads();

        #pragma unroll
        for (int k = 0; k < 32; k++) {
            float4 a0 = *(float4*)(As + k*68 + ri*8);
            float4 a1 = *(float4*)(As + k*68 + ri*8 + 4);
            float4 bv = *(float4*)(Bs + k*128 + ci*4);
            float av[8] = {a0.x,a0.y,a0.z,a0.w,a1.x,a1.y,a1.z,a1.w};
            float bb[4] = {bv.x,bv.y,bv.z,bv.w};
            #pragma unroll
            for (int r = 0; r < 8; r++)
                #pragma unroll
                for (int c = 0; c < 4; c++)
                    acc[r][c] += av[r] * bb[c];
        }
    }

    #pragma unroll
    for (int r = 0; r < 8; r++) {
        float4 o;
        o.x = acc[r][0] + bias[n0 + ci*4 + 0];
        o.y = acc[r][1] + bias[n0 + ci*4 + 1];
        o.z = acc[r][2] + bias[n0 + ci*4 + 2];
        o.w = acc[r][3] + bias[n0 + ci*4 + 3];
        *(float4*)(outp + (size_t)(row0 + ri*8 + r)*H + n0 + ci*4) = o;
    }
}

// ---------------- K5: per-batch GRU scan ------------------------------------------
__global__ void k_scan(const float* __restrict__ Ur, const float* __restrict__ Uh,
                       const int* __restrict__ input_len) {
    int b = blockIdx.x;
    int n = threadIdx.x;               // 256
    __shared__ __align__(16) float h[H];
    __shared__ __align__(16) float rh[H];
    h[n] = 0.0f;
    __syncthreads();
    int len = input_len[b];
    const float* Urn = Ur + n;
    const float* Uhn = Uh + n;

    for (int t = 0; t < len; t++) {
        size_t row = (size_t)(b*T + t) * H;
        // r = sigmoid(preR + h@Ur)
        float s0 = g_preR[row + n], s1 = 0.f, s2 = 0.f, s3 = 0.f;
        const float4* h4 = (const float4*)h;
        #pragma unroll 4
        for (int k4 = 0; k4 < 64; k4++) {
            float4 hv = h4[k4];
            int k = k4 * 4;
            s0 += hv.x * Urn[(k+0)*H];
            s1 += hv.y * Urn[(k+1)*H];
            s2 += hv.z * Urn[(k+2)*H];
            s3 += hv.w * Urn[(k+3)*H];
        }
        float r = sigf(s0 + s1 + s2 + s3);
        float hown = h[n];
        rh[n] = r * hown;
        __syncthreads();               // rh complete; all h reads done

        // hc = tanh(preH + (r*h)@Uh)
        float c0 = g_preH[row + n], c1 = 0.f, c2 = 0.f, c3 = 0.f;
        const float4* rh4 = (const float4*)rh;
        #pragma unroll 4
        for (int k4 = 0; k4 < 64; k4++) {
            float4 rv = rh4[k4];
            int k = k4 * 4;
            c0 += rv.x * Uhn[(k+0)*H];
            c1 += rv.y * Uhn[(k+1)*H];
            c2 += rv.z * Uhn[(k+2)*H];
            c3 += rv.w * Uhn[(k+3)*H];
        }
        float hc = tanhf(c0 + c1 + c2 + c3);
        float gt = g_att[b*T + t];
        float hn = gt * hc + (1.0f - gt) * hown;
        g_eout[row + n] = hn;
        h[n] = hn;                     // only own-slot; others read rh, not h
        __syncthreads();               // h complete before next step's reads
    }
}

// ---------------- K6: span heads --------------------------------------------------
__global__ void k_heads(const int* __restrict__ input_len,
                        const float* __restrict__ Ws, const float* __restrict__ We,
                        float* __restrict__ out) {
    int row  = blockIdx.x * 8 + (threadIdx.x >> 5);   // 8 warps/block
    int lane = threadIdx.x & 31;
    int b = row >> 9, t = row & 511;
    int len = input_len[b];
    float qs = g_qs[b], qe = g_qe[b];
    float os, oe;
    if (t < len) {
        const float* e = g_eout + (size_t)row * H;
        float ds = 0.f, de = 0.f;
        #pragma unroll
        for (int k = lane; k < H; k += 32) {
            float ev = e[k];
            ds += ev * Ws[H + k];
            de += ev * We[H + k];
        }
        #pragma unroll
        for (int off = 16; off; off >>= 1) {
            ds += __shfl_xor_sync(0xFFFFFFFFu, ds, off);
            de += __shfl_xor_sync(0xFFFFFFFFu, de, off);
        }
        os = tanhf(qs + ds);
        oe = tanhf(qe + de);
    } else {
        os = tanhf(qs);
        oe = tanhf(qe);
    }
    if (lane == 0) {
        out[row]      = os;
        out[BT + row] = oe;
    }
}

// ---------------- launch ----------------------------------------------------------
extern "C" void kernel_launch(void* const* d_in, const int* in_sizes, int n_in,
                              void* d_out, int out_size) {
    const float* q   = (const float*)d_in[0];   // [B,H]
    const float* f   = (const float*)d_in[1];   // [B,T,H]
    const int*   len = (const int*)  d_in[2];   // [B]
    const float* W1  = (const float*)d_in[3];   // [7H,H]
    const float* b1  = (const float*)d_in[4];   // [H]
    const float* W2  = (const float*)d_in[5];   // [H,1]
    const float* b2  = (const float*)d_in[6];   // [1]
    const float* Wr  = (const float*)d_in[7];   // [H,H]
    const float* Ur  = (const float*)d_in[8];   // [H,H]
    const float* br  = (const float*)d_in[9];   // [H]
    const float* Wh  = (const float*)d_in[10];  // [H,H]
    const float* Uh  = (const float*)d_in[11];  // [H,H]
    const float* bh  = (const float*)d_in[12];  // [H]
    const float* Ws  = (const float*)d_in[13];  // [2H,1]
    const float* bs  = (const float*)d_in[14];  // [1]
    const float* We  = (const float*)d_in[15];  // [2H,1]
    const float* be  = (const float*)d_in[16];  // [1]
    float* out = (float*)d_out;                 // [2*B*T]

    k_qw<<<B, H>>>(q, W1, b1);
    k_qsqe<<<1, B>>>(q, Ws, bs, We, be);
    k_att<<<BT/64, 256>>>(f, q, W1, W2, b2);
    k_softmax<<<B, T>>>();
    k_pre<<<dim3(BT/64, 4), 256>>>(f, Wr, br, Wh, bh);
    k_scan<<<B, H>>>(Ur, Uh, len);
    k_heads<<<BT/8, 256>>>(len, Ws, We, out);
}

// round 3
// speedup vs baseline: 3.3052x; 3.3052x over previous
#include <cuda_runtime.h>
#include <math.h>

#define B  64
#define T  512
#define H  256
#define BT (B*T)

// ---------------- scratch (device globals: no allocation allowed) ----------------
__device__ float g_qW[B*H];                 // b1 + q@(W1_1+W1_2)
__device__ float g_att[BT];                 // att scores -> softmax g (in place)
__device__ float g_preR[BT*H];              // f@Wr + br
__device__ float g_preH[BT*H];              // f@Wh + bh
__device__ float g_eout[BT*H];              // GRU outputs (valid rows only)
__device__ float g_qs[B];                   // bs + q@Ws[:H]
__device__ float g_qe[B];                   // be + q@We[:H]

__device__ __forceinline__ float sigf(float x) { return 1.0f / (1.0f + expf(-x)); }

// ---------------- K1: qW[b,n] = b1[n] + sum_k q[b,k]*(W1[H+k,n]+W1[2H+k,n]) ------
__global__ void k_qw(const float* __restrict__ q, const float* __restrict__ W1,
                     const float* __restrict__ b1) {
    int b = blockIdx.x, n = threadIdx.x;
    __shared__ float qs[H];
    qs[n] = q[b*H + n];
    __syncthreads();
    float a0 = 0.f, a1 = 0.f, a2 = 0.f, a3 = 0.f;
    const float* wa = W1 + 1*H*H + n;
    const float* wb = W1 + 2*H*H + n;
    #pragma unroll 4
    for (int k = 0; k < H; k += 4) {
        a0 += qs[k+0] * (wa[(k+0)*H] + wb[(k+0)*H]);
        a1 += qs[k+1] * (wa[(k+1)*H] + wb[(k+1)*H]);
        a2 += qs[k+2] * (wa[(k+2)*H] + wb[(k+2)*H]);
        a3 += qs[k+3] * (wa[(k+3)*H] + wb[(k+3)*H]);
    }
    g_qW[b*H + n] = b1[n] + a0 + a1 + a2 + a3;
}

// ---------------- K1b: qs[b] = bs + q[b]@Ws[:H];  qe[b] = be + q[b]@We[:H] -------
__global__ void k_qsqe(const float* __restrict__ q, const float* __restrict__ Ws,
                       const float* __restrict__ bs_, const float* __restrict__ We,
                       const float* __restrict__ be_) {
    int b = threadIdx.x;  // 64 threads
    float s = bs_[0], e = be_[0];
    #pragma unroll 4
    for (int k = 0; k < H; k++) {
        float qv = q[b*H + k];
        s += qv * Ws[k];
        e += qv * We[k];
    }
    g_qs[b] = s;
    g_qe[b] = e;
}

// ---------------- K2: attention scores --------------------------------------------
// att[row] = b2 + sum_n tanh( qW[b,n] + sum_k A[row,k]*Wc[k,n] ) * W2[n]
// A segments (K=768): f, f*q, |f-q|.  Tile 64 rows x 256 cols, 8x8 microtile.
__launch_bounds__(256, 2)
__global__ void k_att(const float* __restrict__ f, const float* __restrict__ q,
                      const float* __restrict__ W1, const float* __restrict__ W2,
                      const float* __restrict__ b2) {
    __shared__ __align__(16) float As[32*68];    // [k][row], padded stride 68
    __shared__ __align__(16) float Bs[32*256];   // [k][n]
    __shared__ float qs[H], qWs[H], W2s[H];

    int tid  = threadIdx.x;
    int tile = blockIdx.x;            // 0..511
    int row0 = tile * 64;
    int b    = tile >> 3;             // 8 tiles per batch (512 rows/batch)

    qs[tid]  = q[b*H + tid];
    qWs[tid] = g_qW[b*H + tid];
    W2s[tid] = W2[tid];

    int ri = tid >> 5;                // 0..7  (row group of 8)
    int ci = tid & 31;                // 0..31 (col group of 8)

    float acc[8][8];
    #pragma unroll
    for (int r = 0; r < 8; r++)
        #pragma unroll
        for (int c = 0; c < 8; c++) acc[r][c] = 0.0f;

    for (int seg = 0; seg < 3; seg++) {
        const float* wA;
        const float* wB;
        bool two;
        if (seg == 0)      { wA = W1;           wB = W1;           two = false; }
        else if (seg == 1) { wA = W1 + 3*H*H;   wB = W1 + 4*H*H;   two = true;  }
        else               { wA = W1 + 5*H*H;   wB = W1 + 6*H*H;   two = true;  }

        for (int kt = 0; kt < 8; kt++) {
            __syncthreads();
            // A tile: 64 rows x 32 k, transformed on the fly, stored [k][row]
            #pragma unroll
            for (int i = 0; i < 2; i++) {
                int f4 = tid + i*256;
                int rr = f4 >> 3, k4 = f4 & 7;
                float4 v = *(const float4*)(f + (size_t)(row0+rr)*H + kt*32 + k4*4);
                float a0, a1, a2, a3;
                if (seg == 0) { a0 = v.x; a1 = v.y; a2 = v.z; a3 = v.w; }
                else {
                    float q0 = qs[kt*32 + k4*4 + 0];
                    float q1 = qs[kt*32 + k4*4 + 1];
                    float q2 = qs[kt*32 + k4*4 + 2];
                    float q3 = qs[kt*32 + k4*4 + 3];
                    if (seg == 1) { a0 = v.x*q0; a1 = v.y*q1; a2 = v.z*q2; a3 = v.w*q3; }
                    else { a0 = fabsf(v.x-q0); a1 = fabsf(v.y-q1); a2 = fabsf(v.z-q2); a3 = fabsf(v.w-q3); }
                }
                As[(k4*4+0)*68 + rr] = a0;
                As[(k4*4+1)*68 + rr] = a1;
                As[(k4*4+2)*68 + rr] = a2;
                As[(k4*4+3)*68 + rr] = a3;
            }
            // B tile: 32 k x 256 n (combine the two W1 blocks for seg 1/2)
            #pragma unroll
            for (int i = 0; i < 8; i++) {
                int f4 = tid + i*256;
                int kk = f4 >> 6, nn = (f4 & 63) * 4;
                float4 w = *(const float4*)(wA + (size_t)(kt*32+kk)*H + nn);
                if (two) {
                    float4 w2 = *(const float4*)(wB + (size_t)(kt*32+kk)*H + nn);
                    w.x += w2.x; w.y += w2.y; w.z += w2.z; w.w += w2.w;
                }
                *(float4*)(Bs + kk*256 + nn) = w;
            }
            __syncthreads();

            #pragma unroll
            for (int k = 0; k < 32; k++) {
                float4 a0 = *(float4*)(As + k*68 + ri*8);
                float4 a1 = *(float4*)(As + k*68 + ri*8 + 4);
                float4 b0 = *(float4*)(Bs + k*256 + ci*8);
                float4 b1 = *(float4*)(Bs + k*256 + ci*8 + 4);
                float av[8] = {a0.x,a0.y,a0.z,a0.w,a1.x,a1.y,a1.z,a1.w};
                float bv[8] = {b0.x,b0.y,b0.z,b0.w,b1.x,b1.y,b1.z,b1.w};
                #pragma unroll
                for (int r = 0; r < 8; r++)
                    #pragma unroll
                    for (int c = 0; c < 8; c++)
                        acc[r][c] += av[r] * bv[c];
            }
        }
    }

    // epilogue: tanh, dot with W2, reduce over the 32 col groups
    __syncthreads();
    float* part = As;                  // reuse: 64*33 = 2112 <= 2176
    float b2v = b2[0];
    #pragma unroll
    for (int r = 0; r < 8; r++) {
        float p = 0.0f;
        #pragma unroll
        for (int c = 0; c < 8; c++) {
            int n = ci*8 + c;
            p += tanhf(acc[r][c] + qWs[n]) * W2s[n];
        }
        part[(ri*8 + r)*33 + ci] = p;
    }
    __syncthreads();
    if (tid < 64) {
        float s = b2v;
        #pragma unroll 8
        for (int c = 0; c < 32; c++) s += part[tid*33 + c];
        g_att[row0 + tid] = s;
    }
}

// ---------------- K4: softmax over T per batch ------------------------------------
__global__ void k_softmax() {
    int b = blockIdx.x, t = threadIdx.x;  // 512 threads
    __shared__ float red[512];
    float v = g_att[b*T + t];
    red[t] = v;
    __syncthreads();
    for (int s = 256; s > 0; s >>= 1) {
        if (t < s) red[t] = fmaxf(red[t], red[t+s]);
        __syncthreads();
    }
    float mx = red[0];
    __syncthreads();
    float e = expf(v - mx);
    red[t] = e;
    __syncthreads();
    for (int s = 256; s > 0; s >>= 1) {
        if (t < s) red[t] += red[t+s];
        __syncthreads();
    }
    g_att[b*T + t] = e / red[0];
}

// ---------------- K3: preR = f@Wr + br, preH = f@Wh + bh --------------------------
// grid (512, 4): y in {0,1} -> Wr cols [y*128,..); y in {2,3} -> Wh.
__launch_bounds__(256, 2)
__global__ void k_pre(const float* __restrict__ f,
                      const float* __restrict__ Wr, const float* __restrict__ br,
                      const float* __restrict__ Wh, const float* __restrict__ bh) {
    __shared__ __align__(16) float As[32*68];
    __shared__ __align__(16) float Bs[32*128];
    int tid  = threadIdx.x;
    int row0 = blockIdx.x * 64;
    int y    = blockIdx.y;
    const float* W    = (y < 2) ? Wr : Wh;
    const float* bias = (y < 2) ? br : bh;
    float*       outp = (y < 2) ? g_preR : g_preH;
    int n0 = (y & 1) * 128;
    int ri = tid >> 5, ci = tid & 31;     // 8 rows x 4 cols microtile

    float acc[8][4];
    #pragma unroll
    for (int r = 0; r < 8; r++)
        #pragma unroll
        for (int c = 0; c < 4; c++) acc[r][c] = 0.0f;

    for (int kt = 0; kt < 8; kt++) {
        __syncthreads();
        #pragma unroll
        for (int i = 0; i < 2; i++) {
            int f4 = tid + i*256;
            int rr = f4 >> 3, k4 = f4 & 7;
            float4 v = *(const float4*)(f + (size_t)(row0+rr)*H + kt*32 + k4*4);
            As[(k4*4+0)*68 + rr] = v.x;
            As[(k4*4+1)*68 + rr] = v.y;
            As[(k4*4+2)*68 + rr] = v.z;
            As[(k4*4+3)*68 + rr] = v.w;
        }
        #pragma unroll
        for (int i = 0; i < 4; i++) {
            int f4 = tid + i*256;
            int kk = f4 >> 5, nn = (f4 & 31) * 4;
            *(float4*)(Bs + kk*128 + nn) =
                *(const float4*)(W + (size_t)(kt*32+kk)*H + n0 + nn);
        }
        __syncthreads();

        #pragma unroll
        for (int k = 0; k < 32; k++) {
            float4 a0 = *(float4*)(As + k*68 + ri*8);
            float4 a1 = *(float4*)(As + k*68 + ri*8 + 4);
            float4 bv = *(float4*)(Bs + k*128 + ci*4);
            float av[8] = {a0.x,a0.y,a0.z,a0.w,a1.x,a1.y,a1.z,a1.w};
            float bb[4] = {bv.x,bv.y,bv.z,bv.w};
            #pragma unroll
            for (int r = 0; r < 8; r++)
                #pragma unroll
                for (int c = 0; c < 4; c++)
                    acc[r][c] += av[r] * bb[c];
        }
    }

    #pragma unroll
    for (int r = 0; r < 8; r++) {
        float4 o;
        o.x = acc[r][0] + bias[n0 + ci*4 + 0];
        o.y = acc[r][1] + bias[n0 + ci*4 + 1];
        o.z = acc[r][2] + bias[n0 + ci*4 + 2];
        o.w = acc[r][3] + bias[n0 + ci*4 + 3];
        *(float4*)(outp + (size_t)(row0 + ri*8 + r)*H + n0 + ci*4) = o;
    }
}

// ---------------- K5: per-batch GRU scan (512 threads, split-k, LDG.128) ----------
// Thread (ko = tid>>6 in 0..7, j = tid&63) computes partial sums over
// k in [32*ko, 32*ko+32) for the 4 outputs n = 4j..4j+3, loading U rows as
// float4 (fully coalesced LDG.128, all addresses step-invariant -> deep MLP).
// Partials reduced via smem red[8][256].
__launch_bounds__(512, 1)
__global__ void k_scan(const float* __restrict__ Ur, const float* __restrict__ Uh,
                       const int* __restrict__ input_len) {
    int b   = blockIdx.x;
    int tid = threadIdx.x;             // 512
    int ko  = tid >> 6;                // 0..7
    int j   = tid & 63;                // 0..63 -> outputs 4j..4j+3
    int k0  = ko * 32;

    __shared__ __align__(16) float h[H];
    __shared__ __align__(16) float rh[H];
    __shared__ __align__(16) float red[8*H];
    __shared__ float gs[T];

    if (tid < H) h[tid] = 0.0f;
    gs[tid] = g_att[b*T + tid];        // 512 g values
    __syncthreads();

    int len = input_len[b];
    const float4* Ur4 = (const float4*)(Ur + (size_t)k0*H) + j;  // rows k0.., col 4j
    const float4* Uh4 = (const float4*)(Uh + (size_t)k0*H) + j;
    const int rowstride4 = H/4;        // float4 stride per k row

    for (int t = 0; t < len; t++) {
        size_t row = (size_t)(b*T + t) * H;

        // prefetch the per-step vectors early (consumed after the barrier)
        float pre_r = 0.f, pre_h = 0.f, hown = 0.f;
        if (tid < H) {
            pre_r = g_preR[row + tid];
            pre_h = g_preH[row + tid];
            hown  = h[tid];
        }

        // ---- partials of h @ Ur ----
        float4 acc = make_float4(0.f, 0.f, 0.f, 0.f);
        #pragma unroll
        for (int kk = 0; kk < 32; kk++) {
            float4 u = Ur4[kk * rowstride4];
            float hv = h[k0 + kk];
            acc.x += hv * u.x; acc.y += hv * u.y;
            acc.z += hv * u.z; acc.w += hv * u.w;
        }
        *(float4*)(red + ko*H + 4*j) = acc;
        __syncthreads();

        // ---- r gate, rh ----
        if (tid < H) {
            float s = pre_r;
            #pragma unroll
            for (int p = 0; p < 8; p++) s += red[p*H + tid];
            float r = sigf(s);
            rh[tid] = r * hown;
        }
        __syncthreads();

        // ---- partials of rh @ Uh ----
        acc = make_float4(0.f, 0.f, 0.f, 0.f);
        #pragma unroll
        for (int kk = 0; kk < 32; kk++) {
            float4 u = Uh4[kk * rowstride4];
            float rv = rh[k0 + kk];
            acc.x += rv * u.x; acc.y += rv * u.y;
            acc.z += rv * u.z; acc.w += rv * u.w;
        }
        *(float4*)(red + ko*H + 4*j) = acc;
        __syncthreads();

        // ---- candidate, blend, write ----
        if (tid < H) {
            float s = pre_h;
            #pragma unroll
            for (int p = 0; p < 8; p++) s += red[p*H + tid];
            float hc = tanhf(s);
            float gt = gs[t];
            float hn = gt * hc + (1.0f - gt) * hown;
            g_eout[row + tid] = hn;
            h[tid] = hn;
        }
        __syncthreads();
    }
}

// ---------------- K6: span heads --------------------------------------------------
__global__ void k_heads(const int* __restrict__ input_len,
                        const float* __restrict__ Ws, const float* __restrict__ We,
                        float* __restrict__ out) {
    int row  = blockIdx.x * 8 + (threadIdx.x >> 5);   // 8 warps/block
    int lane = threadIdx.x & 31;
    int b = row >> 9, t = row & 511;
    int len = input_len[b];
    float qs = g_qs[b], qe = g_qe[b];
    float os, oe;
    if (t < len) {
        const float* e = g_eout + (size_t)row * H;
        float ds = 0.f, de = 0.f;
        #pragma unroll
        for (int k = lane; k < H; k += 32) {
            float ev = e[k];
            ds += ev * Ws[H + k];
            de += ev * We[H + k];
        }
        #pragma unroll
        for (int off = 16; off; off >>= 1) {
            ds += __shfl_xor_sync(0xFFFFFFFFu, ds, off);
            de += __shfl_xor_sync(0xFFFFFFFFu, de, off);
        }
        os = tanhf(qs + ds);
        oe = tanhf(qe + de);
    } else {
        os = tanhf(qs);
        oe = tanhf(qe);
    }
    if (lane == 0) {
        out[row]      = os;
        out[BT + row] = oe;
    }
}

// ---------------- launch ----------------------------------------------------------
extern "C" void kernel_launch(void* const* d_in, const int* in_sizes, int n_in,
                              void* d_out, int out_size) {
    const float* q   = (const float*)d_in[0];   // [B,H]
    const float* f   = (const float*)d_in[1];   // [B,T,H]
    const int*   len = (const int*)  d_in[2];   // [B]
    const float* W1  = (const float*)d_in[3];   // [7H,H]
    const float* b1  = (const float*)d_in[4];   // [H]
    const float* W2  = (const float*)d_in[5];   // [H,1]
    const float* b2  = (const float*)d_in[6];   // [1]
    const float* Wr  = (const float*)d_in[7];   // [H,H]
    const float* Ur  = (const float*)d_in[8];   // [H,H]
    const float* br  = (const float*)d_in[9];   // [H]
    const float* Wh  = (const float*)d_in[10];  // [H,H]
    const float* Uh  = (const float*)d_in[11];  // [H,H]
    const float* bh  = (const float*)d_in[12];  // [H]
    const float* Ws  = (const float*)d_in[13];  // [2H,1]
    const float* bs  = (const float*)d_in[14];  // [1]
    const float* We  = (const float*)d_in[15];  // [2H,1]
    const float* be  = (const float*)d_in[16];  // [1]
    float* out = (float*)d_out;                 // [2*B*T]

    k_qw<<<B, H>>>(q, W1, b1);
    k_qsqe<<<1, B>>>(q, Ws, bs, We, be);
    k_att<<<BT/64, 256>>>(f, q, W1, W2, b2);
    k_softmax<<<B, T>>>();
    k_pre<<<dim3(BT/64, 4), 256>>>(f, Wr, br, Wh, bh);
    k_scan<<<B, 512>>>(Ur, Uh, len);
    k_heads<<<BT/8, 256>>>(len, Ws, We, out);
}

// round 4
// speedup vs baseline: 6.4194x; 1.9422x over previous
#include <cuda_runtime.h>
#include <cuda_fp16.h>
#include <math.h>

#define B  64
#define T  512
#define H  256
#define BT (B*T)

// ---------------- scratch (device globals: no allocation allowed) ----------------
__device__ float  g_qW[B*H];                 // b1 + q@(W1_1+W1_2)
__device__ float  g_att[BT];                 // att scores -> softmax g (in place)
__device__ float  g_preR[BT*H];              // f@Wr + br
__device__ float  g_preH[BT*H];              // f@Wh + bh
__device__ float  g_eout[BT*H];              // GRU outputs (valid rows only)
__device__ float  g_qs[B];                   // bs + q@Ws[:H]
__device__ float  g_qe[B];                   // be + q@We[:H]
__device__ __half g_Urh[H*H];                // fp16 copy of Ur
__device__ __half g_Uhh[H*H];                // fp16 copy of Uh

__device__ __forceinline__ float sigf(float x) { return 1.0f / (1.0f + expf(-x)); }

// ---------------- K0: convert Ur/Uh to fp16 ---------------------------------------
__global__ void k_cvt(const float* __restrict__ Ur, const float* __restrict__ Uh) {
    int i = blockIdx.x * 512 + threadIdx.x;   // grid 128 x 512 = 65536
    g_Urh[i] = __float2half(Ur[i]);
    g_Uhh[i] = __float2half(Uh[i]);
}

// ---------------- K1: qW[b,n] = b1[n] + sum_k q[b,k]*(W1[H+k,n]+W1[2H+k,n]) ------
__global__ void k_qw(const float* __restrict__ q, const float* __restrict__ W1,
                     const float* __restrict__ b1) {
    int b = blockIdx.x, n = threadIdx.x;
    __shared__ float qs[H];
    qs[n] = q[b*H + n];
    __syncthreads();
    float a0 = 0.f, a1 = 0.f, a2 = 0.f, a3 = 0.f;
    const float* wa = W1 + 1*H*H + n;
    const float* wb = W1 + 2*H*H + n;
    #pragma unroll 4
    for (int k = 0; k < H; k += 4) {
        a0 += qs[k+0] * (wa[(k+0)*H] + wb[(k+0)*H]);
        a1 += qs[k+1] * (wa[(k+1)*H] + wb[(k+1)*H]);
        a2 += qs[k+2] * (wa[(k+2)*H] + wb[(k+2)*H]);
        a3 += qs[k+3] * (wa[(k+3)*H] + wb[(k+3)*H]);
    }
    g_qW[b*H + n] = b1[n] + a0 + a1 + a2 + a3;
}

// ---------------- K1b: qs[b] = bs + q[b]@Ws[:H];  qe[b] = be + q[b]@We[:H] -------
__global__ void k_qsqe(const float* __restrict__ q, const float* __restrict__ Ws,
                       const float* __restrict__ bs_, const float* __restrict__ We,
                       const float* __restrict__ be_) {
    int b = threadIdx.x;  // 64 threads
    float s = bs_[0], e = be_[0];
    #pragma unroll 4
    for (int k = 0; k < H; k++) {
        float qv = q[b*H + k];
        s += qv * Ws[k];
        e += qv * We[k];
    }
    g_qs[b] = s;
    g_qe[b] = e;
}

// ---------------- K2: attention scores --------------------------------------------
// att[row] = b2 + sum_n tanh( qW[b,n] + sum_k A[row,k]*Wc[k,n] ) * W2[n]
// A segments (K=768): f, f*q, |f-q|.  Tile 64 rows x 256 cols, 8x8 microtile.
__launch_bounds__(256, 2)
__global__ void k_att(const float* __restrict__ f, const float* __restrict__ q,
                      const float* __restrict__ W1, const float* __restrict__ W2,
                      const float* __restrict__ b2) {
    __shared__ __align__(16) float As[32*68];    // [k][row], padded stride 68
    __shared__ __align__(16) float Bs[32*256];   // [k][n]
    __shared__ float qs[H], qWs[H], W2s[H];

    int tid  = threadIdx.x;
    int tile = blockIdx.x;            // 0..511
    int row0 = tile * 64;
    int b    = tile >> 3;             // 8 tiles per batch (512 rows/batch)

    qs[tid]  = q[b*H + tid];
    qWs[tid] = g_qW[b*H + tid];
    W2s[tid] = W2[tid];

    int ri = tid >> 5;                // 0..7  (row group of 8)
    int ci = tid & 31;                // 0..31 (col group of 8)

    float acc[8][8];
    #pragma unroll
    for (int r = 0; r < 8; r++)
        #pragma unroll
        for (int c = 0; c < 8; c++) acc[r][c] = 0.0f;

    for (int seg = 0; seg < 3; seg++) {
        const float* wA;
        const float* wB;
        bool two;
        if (seg == 0)      { wA = W1;           wB = W1;           two = false; }
        else if (seg == 1) { wA = W1 + 3*H*H;   wB = W1 + 4*H*H;   two = true;  }
        else               { wA = W1 + 5*H*H;   wB = W1 + 6*H*H;   two = true;  }

        for (int kt = 0; kt < 8; kt++) {
            __syncthreads();
            // A tile: 64 rows x 32 k, transformed on the fly, stored [k][row]
            #pragma unroll
            for (int i = 0; i < 2; i++) {
                int f4 = tid + i*256;
                int rr = f4 >> 3, k4 = f4 & 7;
                float4 v = *(const float4*)(f + (size_t)(row0+rr)*H + kt*32 + k4*4);
                float a0, a1, a2, a3;
                if (seg == 0) { a0 = v.x; a1 = v.y; a2 = v.z; a3 = v.w; }
                else {
                    float q0 = qs[kt*32 + k4*4 + 0];
                    float q1 = qs[kt*32 + k4*4 + 1];
                    float q2 = qs[kt*32 + k4*4 + 2];
                    float q3 = qs[kt*32 + k4*4 + 3];
                    if (seg == 1) { a0 = v.x*q0; a1 = v.y*q1; a2 = v.z*q2; a3 = v.w*q3; }
                    else { a0 = fabsf(v.x-q0); a1 = fabsf(v.y-q1); a2 = fabsf(v.z-q2); a3 = fabsf(v.w-q3); }
                }
                As[(k4*4+0)*68 + rr] = a0;
                As[(k4*4+1)*68 + rr] = a1;
                As[(k4*4+2)*68 + rr] = a2;
                As[(k4*4+3)*68 + rr] = a3;
            }
            // B tile: 32 k x 256 n (combine the two W1 blocks for seg 1/2)
            #pragma unroll
            for (int i = 0; i < 8; i++) {
                int f4 = tid + i*256;
                int kk = f4 >> 6, nn = (f4 & 63) * 4;
                float4 w = *(const float4*)(wA + (size_t)(kt*32+kk)*H + nn);
                if (two) {
                    float4 w2 = *(const float4*)(wB + (size_t)(kt*32+kk)*H + nn);
                    w.x += w2.x; w.y += w2.y; w.z += w2.z; w.w += w2.w;
                }
                *(float4*)(Bs + kk*256 + nn) = w;
            }
            __syncthreads();

            #pragma unroll
            for (int k = 0; k < 32; k++) {
                float4 a0 = *(float4*)(As + k*68 + ri*8);
                float4 a1 = *(float4*)(As + k*68 + ri*8 + 4);
                float4 b0 = *(float4*)(Bs + k*256 + ci*8);
                float4 b1 = *(float4*)(Bs + k*256 + ci*8 + 4);
                float av[8] = {a0.x,a0.y,a0.z,a0.w,a1.x,a1.y,a1.z,a1.w};
                float bv[8] = {b0.x,b0.y,b0.z,b0.w,b1.x,b1.y,b1.z,b1.w};
                #pragma unroll
                for (int r = 0; r < 8; r++)
                    #pragma unroll
                    for (int c = 0; c < 8; c++)
                        acc[r][c] += av[r] * bv[c];
            }
        }
    }

    // epilogue: tanh, dot with W2, reduce over the 32 col groups
    __syncthreads();
    float* part = As;                  // reuse: 64*33 = 2112 <= 2176
    float b2v = b2[0];
    #pragma unroll
    for (int r = 0; r < 8; r++) {
        float p = 0.0f;
        #pragma unroll
        for (int c = 0; c < 8; c++) {
            int n = ci*8 + c;
            p += tanhf(acc[r][c] + qWs[n]) * W2s[n];
        }
        part[(ri*8 + r)*33 + ci] = p;
    }
    __syncthreads();
    if (tid < 64) {
        float s = b2v;
        #pragma unroll 8
        for (int c = 0; c < 32; c++) s += part[tid*33 + c];
        g_att[row0 + tid] = s;
    }
}

// ---------------- K4: softmax over T per batch ------------------------------------
__global__ void k_softmax() {
    int b = blockIdx.x, t = threadIdx.x;  // 512 threads
    __shared__ float red[512];
    float v = g_att[b*T + t];
    red[t] = v;
    __syncthreads();
    for (int s = 256; s > 0; s >>= 1) {
        if (t < s) red[t] = fmaxf(red[t], red[t+s]);
        __syncthreads();
    }
    float mx = red[0];
    __syncthreads();
    float e = expf(v - mx);
    red[t] = e;
    __syncthreads();
    for (int s = 256; s > 0; s >>= 1) {
        if (t < s) red[t] += red[t+s];
        __syncthreads();
    }
    g_att[b*T + t] = e / red[0];
}

// ---------------- K3: preR = f@Wr + br, preH = f@Wh + bh --------------------------
// grid (512, 4): y in {0,1} -> Wr cols [y*128,..); y in {2,3} -> Wh.
__launch_bounds__(256, 2)
__global__ void k_pre(const float* __restrict__ f,
                      const float* __restrict__ Wr, const float* __restrict__ br,
                      const float* __restrict__ Wh, const float* __restrict__ bh) {
    __shared__ __align__(16) float As[32*68];
    __shared__ __align__(16) float Bs[32*128];
    int tid  = threadIdx.x;
    int row0 = blockIdx.x * 64;
    int y    = blockIdx.y;
    const float* W    = (y < 2) ? Wr : Wh;
    const float* bias = (y < 2) ? br : bh;
    float*       outp = (y < 2) ? g_preR : g_preH;
    int n0 = (y & 1) * 128;
    int ri = tid >> 5, ci = tid & 31;     // 8 rows x 4 cols microtile

    float acc[8][4];
    #pragma unroll
    for (int r = 0; r < 8; r++)
        #pragma unroll
        for (int c = 0; c < 4; c++) acc[r][c] = 0.0f;

    for (int kt = 0; kt < 8; kt++) {
        __syncthreads();
        #pragma unroll
        for (int i = 0; i < 2; i++) {
            int f4 = tid + i*256;
            int rr = f4 >> 3, k4 = f4 & 7;
            float4 v = *(const float4*)(f + (size_t)(row0+rr)*H + kt*32 + k4*4);
            As[(k4*4+0)*68 + rr] = v.x;
            As[(k4*4+1)*68 + rr] = v.y;
            As[(k4*4+2)*68 + rr] = v.z;
            As[(k4*4+3)*68 + rr] = v.w;
        }
        #pragma unroll
        for (int i = 0; i < 4; i++) {
            int f4 = tid + i*256;
            int kk = f4 >> 5, nn = (f4 & 31) * 4;
            *(float4*)(Bs + kk*128 + nn) =
                *(const float4*)(W + (size_t)(kt*32+kk)*H + n0 + nn);
        }
        __syncthreads();

        #pragma unroll
        for (int k = 0; k < 32; k++) {
            float4 a0 = *(float4*)(As + k*68 + ri*8);
            float4 a1 = *(float4*)(As + k*68 + ri*8 + 4);
            float4 bv = *(float4*)(Bs + k*128 + ci*4);
            float av[8] = {a0.x,a0.y,a0.z,a0.w,a1.x,a1.y,a1.z,a1.w};
            float bb[4] = {bv.x,bv.y,bv.z,bv.w};
            #pragma unroll
            for (int r = 0; r < 8; r++)
                #pragma unroll
                for (int c = 0; c < 4; c++)
                    acc[r][c] += av[r] * bb[c];
        }
    }

    #pragma unroll
    for (int r = 0; r < 8; r++) {
        float4 o;
        o.x = acc[r][0] + bias[n0 + ci*4 + 0];
        o.y = acc[r][1] + bias[n0 + ci*4 + 1];
        o.z = acc[r][2] + bias[n0 + ci*4 + 2];
        o.w = acc[r][3] + bias[n0 + ci*4 + 3];
        *(float4*)(outp + (size_t)(row0 + ri*8 + r)*H + n0 + ci*4) = o;
    }
}

// ---------------- K5: per-batch GRU scan (fp16 U, 512 threads, split-k) -----------
// Warp w (0..15) owns k-slice [16w, 16w+16); lane l owns outputs n = 8l..8l+7.
// Each (w,l) thread loads uint4 = 8 halves per k row -> coalesced LDG.128.
// Partials (fp32) reduced via red[16][256].
__launch_bounds__(512, 1)
__global__ void k_scan(const int* __restrict__ input_len) {
    int b    = blockIdx.x;
    int tid  = threadIdx.x;            // 512
    int w    = tid >> 5;               // 0..15 (k-split)
    int l    = tid & 31;               // 0..31 -> outputs 8l..8l+7
    int k0   = w * 16;
    int n0   = l * 8;

    __shared__ __align__(16) float h[H];
    __shared__ __align__(16) float rh[H];
    __shared__ __align__(16) float red[16*H];
    __shared__ float gs[T];

    if (tid < H) h[tid] = 0.0f;
    gs[tid] = g_att[b*T + tid];        // 512 g values
    __syncthreads();

    int len = input_len[b];
    const uint4* Ur4 = (const uint4*)(g_Urh + (size_t)k0*H + n0);  // stride H halves = 1 uint4 row of 32
    const uint4* Uh4 = (const uint4*)(g_Uhh + (size_t)k0*H + n0);
    const int rs = H/8;                // uint4 stride per k row (256 halves / 8)

    for (int t = 0; t < len; t++) {
        size_t row = (size_t)(b*T + t) * H;

        float pre_r = 0.f, pre_h = 0.f, hown = 0.f;
        if (tid < H) {
            pre_r = g_preR[row + tid];
            pre_h = g_preH[row + tid];
            hown  = h[tid];
        }

        // ---- partials of h @ Ur ----
        float a0=0.f,a1=0.f,a2=0.f,a3=0.f,a4=0.f,a5=0.f,a6=0.f,a7=0.f;
        #pragma unroll
        for (int kk = 0; kk < 16; kk++) {
            uint4 u = Ur4[kk * rs];
            const __half2* hu = (const __half2*)&u;
            float hv = h[k0 + kk];
            float2 p0 = __half22float2(hu[0]);
            float2 p1 = __half22float2(hu[1]);
            float2 p2 = __half22float2(hu[2]);
            float2 p3 = __half22float2(hu[3]);
            a0 += hv*p0.x; a1 += hv*p0.y; a2 += hv*p1.x; a3 += hv*p1.y;
            a4 += hv*p2.x; a5 += hv*p2.y; a6 += hv*p3.x; a7 += hv*p3.y;
        }
        {
            float4* o = (float4*)(red + w*H + n0);
            o[0] = make_float4(a0,a1,a2,a3);
            o[1] = make_float4(a4,a5,a6,a7);
        }
        __syncthreads();

        // ---- r gate, rh ----
        if (tid < H) {
            float s = pre_r;
            #pragma unroll
            for (int p = 0; p < 16; p++) s += red[p*H + tid];
            float r = sigf(s);
            rh[tid] = r * hown;
        }
        __syncthreads();

        // ---- partials of rh @ Uh ----
        a0=0.f;a1=0.f;a2=0.f;a3=0.f;a4=0.f;a5=0.f;a6=0.f;a7=0.f;
        #pragma unroll
        for (int kk = 0; kk < 16; kk++) {
            uint4 u = Uh4[kk * rs];
            const __half2* hu = (const __half2*)&u;
            float rv = rh[k0 + kk];
            float2 p0 = __half22float2(hu[0]);
            float2 p1 = __half22float2(hu[1]);
            float2 p2 = __half22float2(hu[2]);
            float2 p3 = __half22float2(hu[3]);
            a0 += rv*p0.x; a1 += rv*p0.y; a2 += rv*p1.x; a3 += rv*p1.y;
            a4 += rv*p2.x; a5 += rv*p2.y; a6 += rv*p3.x; a7 += rv*p3.y;
        }
        {
            float4* o = (float4*)(red + w*H + n0);
            o[0] = make_float4(a0,a1,a2,a3);
            o[1] = make_float4(a4,a5,a6,a7);
        }
        __syncthreads();

        // ---- candidate, blend, write ----
        if (tid < H) {
            float s = pre_h;
            #pragma unroll
            for (int p = 0; p < 16; p++) s += red[p*H + tid];
            float hc = tanhf(s);
            float gt = gs[t];
            float hn = gt * hc + (1.0f - gt) * hown;
            g_eout[row + tid] = hn;
            h[tid] = hn;
        }
        __syncthreads();
    }
}

// ---------------- K6: span heads --------------------------------------------------
__global__ void k_heads(const int* __restrict__ input_len,
                        const float* __restrict__ Ws, const float* __restrict__ We,
                        float* __restrict__ out) {
    int row  = blockIdx.x * 8 + (threadIdx.x >> 5);   // 8 warps/block
    int lane = threadIdx.x & 31;
    int b = row >> 9, t = row & 511;
    int len = input_len[b];
    float qs = g_qs[b], qe = g_qe[b];
    float os, oe;
    if (t < len) {
        const float* e = g_eout + (size_t)row * H;
        float ds = 0.f, de = 0.f;
        #pragma unroll
        for (int k = lane; k < H; k += 32) {
            float ev = e[k];
            ds += ev * Ws[H + k];
            de += ev * We[H + k];
        }
        #pragma unroll
        for (int off = 16; off; off >>= 1) {
            ds += __shfl_xor_sync(0xFFFFFFFFu, ds, off);
            de += __shfl_xor_sync(0xFFFFFFFFu, de, off);
        }
        os = tanhf(qs + ds);
        oe = tanhf(qe + de);
    } else {
        os = tanhf(qs);
        oe = tanhf(qe);
    }
    if (lane == 0) {
        out[row]      = os;
        out[BT + row] = oe;
    }
}

// ---------------- launch ----------------------------------------------------------
extern "C" void kernel_launch(void* const* d_in, const int* in_sizes, int n_in,
                              void* d_out, int out_size) {
    const float* q   = (const float*)d_in[0];   // [B,H]
    const float* f   = (const float*)d_in[1];   // [B,T,H]
    const int*   len = (const int*)  d_in[2];   // [B]
    const float* W1  = (const float*)d_in[3];   // [7H,H]
    const float* b1  = (const float*)d_in[4];   // [H]
    const float* W2  = (const float*)d_in[5];   // [H,1]
    const float* b2  = (const float*)d_in[6];   // [1]
    const float* Wr  = (const float*)d_in[7];   // [H,H]
    const float* Ur  = (const float*)d_in[8];   // [H,H]
    const float* br  = (const float*)d_in[9];   // [H]
    const float* Wh  = (const float*)d_in[10];  // [H,H]
    const float* Uh  = (const float*)d_in[11];  // [H,H]
    const float* bh  = (const float*)d_in[12];  // [H]
    const float* Ws  = (const float*)d_in[13];  // [2H,1]
    const float* bs  = (const float*)d_in[14];  // [1]
    const float* We  = (const float*)d_in[15];  // [2H,1]
    const float* be  = (const float*)d_in[16];  // [1]
    float* out = (float*)d_out;                 // [2*B*T]

    // order chosen so the ncu-profiled slot (#4) lands on k_att
    k_pre<<<dim3(BT/64, 4), 256>>>(f, Wr, br, Wh, bh);
    k_cvt<<<H*H/512, 512>>>(Ur, Uh);
    k_qw<<<B, H>>>(q, W1, b1);
    k_att<<<BT/64, 256>>>(f, q, W1, W2, b2);
    k_softmax<<<B, T>>>();
    k_scan<<<B, 512>>>(len);
    k_qsqe<<<1, B>>>(q, Ws, bs, We, be);
    k_heads<<<BT/8, 256>>>(len, Ws, We, out);
}

// round 6
// speedup vs baseline: 6.4679x; 1.0076x over previous
#include <cuda_runtime.h>
#include <cuda_fp16.h>
#include <math.h>

#define B  64
#define T  512
#define H  256
#define BT (B*T)

// ---------------- scratch (device globals: no allocation allowed) ----------------
__device__ float  g_att[BT];                 // raw att scores (softmax fused into scan)
__device__ float  g_preR[BT*H];              // f@Wr + br
__device__ float  g_preH[BT*H];              // f@Wh + bh
__device__ float  g_eout[BT*H];              // GRU outputs (valid rows only)
__device__ float  g_qs[B];                   // bs + q@Ws[:H]
__device__ float  g_qe[B];                   // be + q@We[:H]
__device__ __half g_Urh[H*H];                // fp16 copy of Ur
__device__ __half g_Uhh[H*H];                // fp16 copy of Uh
__device__ float  g_Wc[1024*H];              // [0:256)=W1_0, [256:512)=W1_3+W1_4,
                                             // [512:768)=W1_5+W1_6, [768:1024)=W1_1+W1_2

__device__ __forceinline__ float sigf(float x) { return 1.0f / (1.0f + expf(-x)); }

__device__ __forceinline__ float tanh_fast(float x) {
    float y;
    asm("tanh.approx.f32 %0, %1;" : "=f"(y) : "f"(x));
    return y;
}

__device__ __forceinline__ unsigned smem_u32(const void* p) {
    unsigned a;
    asm("{ .reg .u64 t; cvta.to.shared.u64 t, %1; cvt.u32.u64 %0, t; }"
        : "=r"(a) : "l"(p));
    return a;
}

__device__ __forceinline__ void mbar_init(unsigned mbar, unsigned count) {
    asm volatile("mbarrier.init.shared.b64 [%0], %1;" :: "r"(mbar), "r"(count) : "memory");
}

__device__ __forceinline__ void mbar_arrive_peer(unsigned mbar, unsigned peer) {
    asm volatile(
        "{ .reg .b32 ra;\n\t"
        "mapa.shared::cluster.u32 ra, %0, %1;\n\t"
        "mbarrier.arrive.release.cluster.shared::cluster.b64 _, [ra]; }"
        :: "r"(mbar), "r"(peer) : "memory");
}

__device__ __forceinline__ void mbar_wait_cluster(unsigned mbar, unsigned parity) {
    asm volatile(
        "{ .reg .pred P;\n\t"
        "W%=:\n\t"
        "mbarrier.try_wait.parity.acquire.cluster.shared::cta.b64 P, [%0], %1, 0x989680;\n\t"
        "@!P bra W%=; }"
        :: "r"(mbar), "r"(parity) : "memory");
}

__device__ __forceinline__ void st_peer_f32(unsigned laddr, unsigned peer, float v) {
    asm volatile(
        "{ .reg .b32 ra;\n\t"
        "mapa.shared::cluster.u32 ra, %0, %1;\n\t"
        "st.shared::cluster.f32 [ra], %2; }"
        :: "r"(laddr), "r"(peer), "f"(v) : "memory");
}

__device__ __forceinline__ unsigned ctarank() {
    unsigned r;
    asm("mov.u32 %0, %%cluster_ctarank;" : "=r"(r));
    return r;
}

// ---------------- K0: build Wc and fp16 U copies ----------------------------------
__global__ void k_prep(const float* __restrict__ W1, const float* __restrict__ Ur,
                       const float* __restrict__ Uh) {
    int i = blockIdx.x * 512 + threadIdx.x;   // grid 512 x 512 = 262144
    int r = i >> 8, c = i & 255;
    float v;
    if (r < 256)       v = W1[i];
    else if (r < 512)  v = W1[(r+512)*H + c] + W1[(r+768)*H + c];
    else if (r < 768)  v = W1[(r+768)*H + c] + W1[(r+1024)*H + c];
    else               v = W1[(r-512)*H + c] + W1[(r-256)*H + c];
    g_Wc[i] = v;
    if (i < H*H) {
        g_Urh[i] = __float2half(Ur[i]);
        g_Uhh[i] = __float2half(Uh[i]);
    }
}

// ---------------- K1b: qs[b] = bs + q[b]@Ws[:H];  qe[b] = be + q[b]@We[:H] -------
__global__ void k_qsqe(const float* __restrict__ q, const float* __restrict__ Ws,
                       const float* __restrict__ bs_, const float* __restrict__ We,
                       const float* __restrict__ be_) {
    int b = threadIdx.x;  // 64 threads
    float s = bs_[0], e = be_[0];
    #pragma unroll 4
    for (int k = 0; k < H; k++) {
        float qv = q[b*H + k];
        s += qv * Ws[k];
        e += qv * We[k];
    }
    g_qs[b] = s;
    g_qe[b] = e;
}

// ---------------- K2: attention scores (qW fused, combined weights) ---------------
__launch_bounds__(256, 2)
__global__ void k_att(const float* __restrict__ f, const float* __restrict__ q,
                      const float* __restrict__ b1, const float* __restrict__ W2,
                      const float* __restrict__ b2) {
    __shared__ __align__(16) float As[32*68];    // [k][row], padded stride 68
    __shared__ __align__(16) float Bs[32*256];   // [k][n]
    __shared__ float qs[H], qWs[H], W2s[H];

    int tid  = threadIdx.x;
    int tile = blockIdx.x;            // 0..511
    int row0 = tile * 64;
    int b    = tile >> 3;             // 8 tiles per batch

    qs[tid]  = q[b*H + tid];
    W2s[tid] = W2[tid];
    __syncthreads();

    // fused qW: qW[n=tid] = b1[n] + sum_k qs[k] * Wq[k][n]
    {
        float acc0 = b1[tid];
        const float* Wq = g_Wc + 768*H + tid;
        #pragma unroll 8
        for (int k = 0; k < H; k++) acc0 += qs[k] * Wq[k*H];
        qWs[tid] = acc0;              // visible after first loop barrier
    }

    int ri = tid >> 5;                // 0..7  (row group of 8)
    int ci = tid & 31;                // 0..31 (col group of 8)

    float acc[8][8];
    #pragma unroll
    for (int r = 0; r < 8; r++)
        #pragma unroll
        for (int c = 0; c < 8; c++) acc[r][c] = 0.0f;

    for (int seg = 0; seg < 3; seg++) {
        const float* wA = g_Wc + seg*H*H;

        for (int kt = 0; kt < 8; kt++) {
            __syncthreads();
            // A tile: 64 rows x 32 k, transformed on the fly, stored [k][row]
            #pragma unroll
            for (int i = 0; i < 2; i++) {
                int f4 = tid + i*256;
                int rr = f4 >> 3, k4 = f4 & 7;
                float4 v = *(const float4*)(f + (size_t)(row0+rr)*H + kt*32 + k4*4);
                float a0, a1, a2, a3;
                if (seg == 0) { a0 = v.x; a1 = v.y; a2 = v.z; a3 = v.w; }
                else {
                    float q0 = qs[kt*32 + k4*4 + 0];
                    float q1 = qs[kt*32 + k4*4 + 1];
                    float q2 = qs[kt*32 + k4*4 + 2];
                    float q3 = qs[kt*32 + k4*4 + 3];
                    if (seg == 1) { a0 = v.x*q0; a1 = v.y*q1; a2 = v.z*q2; a3 = v.w*q3; }
                    else { a0 = fabsf(v.x-q0); a1 = fabsf(v.y-q1); a2 = fabsf(v.z-q2); a3 = fabsf(v.w-q3); }
                }
                As[(k4*4+0)*68 + rr] = a0;
                As[(k4*4+1)*68 + rr] = a1;
                As[(k4*4+2)*68 + rr] = a2;
                As[(k4*4+3)*68 + rr] = a3;
            }
            // B tile: 32 k x 256 n (single precombined matrix)
            #pragma unroll
            for (int i = 0; i < 8; i++) {
                int f4 = tid + i*256;
                int kk = f4 >> 6, nn = (f4 & 63) * 4;
                *(float4*)(Bs + kk*256 + nn) =
                    *(const float4*)(wA + (size_t)(kt*32+kk)*H + nn);
            }
            __syncthreads();

            #pragma unroll
            for (int k = 0; k < 32; k++) {
                float4 a0 = *(float4*)(As + k*68 + ri*8);
                float4 a1 = *(float4*)(As + k*68 + ri*8 + 4);
                float4 b0 = *(float4*)(Bs + k*256 + ci*8);
                float4 b1v = *(float4*)(Bs + k*256 + ci*8 + 4);
                float av[8] = {a0.x,a0.y,a0.z,a0.w,a1.x,a1.y,a1.z,a1.w};
                float bv[8] = {b0.x,b0.y,b0.z,b0.w,b1v.x,b1v.y,b1v.z,b1v.w};
                #pragma unroll
                for (int r = 0; r < 8; r++)
                    #pragma unroll
                    for (int c = 0; c < 8; c++)
                        acc[r][c] += av[r] * bv[c];
            }
        }
    }

    // epilogue: tanh, dot with W2, reduce over the 32 col groups
    __syncthreads();
    float* part = As;                  // reuse: 64*33 = 2112 <= 2176
    float b2v = b2[0];
    #pragma unroll
    for (int r = 0; r < 8; r++) {
        float p = 0.0f;
        #pragma unroll
        for (int c = 0; c < 8; c++) {
            int n = ci*8 + c;
            p += tanh_fast(acc[r][c] + qWs[n]) * W2s[n];
        }
        part[(ri*8 + r)*33 + ci] = p;
    }
    __syncthreads();
    if (tid < 64) {
        float s = b2v;
        #pragma unroll 8
        for (int c = 0; c < 32; c++) s += part[tid*33 + c];
        g_att[row0 + tid] = s;
    }
}

// ---------------- K3: preR = f@Wr + br, preH = f@Wh + bh --------------------------
__launch_bounds__(256, 2)
__global__ void k_pre(const float* __restrict__ f,
                      const float* __restrict__ Wr, const float* __restrict__ br,
                      const float* __restrict__ Wh, const float* __restrict__ bh) {
    __shared__ __align__(16) float As[32*68];
    __shared__ __align__(16) float Bs[32*128];
    int tid  = threadIdx.x;
    int row0 = blockIdx.x * 64;
    int y    = blockIdx.y;
    const float* W    = (y < 2) ? Wr : Wh;
    const float* bias = (y < 2) ? br : bh;
    float*       outp = (y < 2) ? g_preR : g_preH;
    int n0 = (y & 1) * 128;
    int ri = tid >> 5, ci = tid & 31;     // 8 rows x 4 cols microtile

    float acc[8][4];
    #pragma unroll
    for (int r = 0; r < 8; r++)
        #pragma unroll
        for (int c = 0; c < 4; c++) acc[r][c] = 0.0f;

    for (int kt = 0; kt < 8; kt++) {
        __syncthreads();
        #pragma unroll
        for (int i = 0; i < 2; i++) {
            int f4 = tid + i*256;
            int rr = f4 >> 3, k4 = f4 & 7;
            float4 v = *(const float4*)(f + (size_t)(row0+rr)*H + kt*32 + k4*4);
            As[(k4*4+0)*68 + rr] = v.x;
            As[(k4*4+1)*68 + rr] = v.y;
            As[(k4*4+2)*68 + rr] = v.z;
            As[(k4*4+3)*68 + rr] = v.w;
        }
        #pragma unroll
        for (int i = 0; i < 4; i++) {
            int f4 = tid + i*256;
            int kk = f4 >> 5, nn = (f4 & 31) * 4;
            *(float4*)(Bs + kk*128 + nn) =
                *(const float4*)(W + (size_t)(kt*32+kk)*H + n0 + nn);
        }
        __syncthreads();

        #pragma unroll
        for (int k = 0; k < 32; k++) {
            float4 a0 = *(float4*)(As + k*68 + ri*8);
            float4 a1 = *(float4*)(As + k*68 + ri*8 + 4);
            float4 bv = *(float4*)(Bs + k*128 + ci*4);
            float av[8] = {a0.x,a0.y,a0.z,a0.w,a1.x,a1.y,a1.z,a1.w};
            float bb[4] = {bv.x,bv.y,bv.z,bv.w};
            #pragma unroll
            for (int r = 0; r < 8; r++)
                #pragma unroll
                for (int c = 0; c < 4; c++)
                    acc[r][c] += av[r] * bb[c];
        }
    }

    #pragma unroll
    for (int r = 0; r < 8; r++) {
        float4 o;
        o.x = acc[r][0] + bias[n0 + ci*4 + 0];
        o.y = acc[r][1] + bias[n0 + ci*4 + 1];
        o.z = acc[r][2] + bias[n0 + ci*4 + 2];
        o.w = acc[r][3] + bias[n0 + ci*4 + 3];
        *(float4*)(outp + (size_t)(row0 + ri*8 + r)*H + n0 + ci*4) = o;
    }
}

// ---------------- K5: GRU scan, 2-CTA cluster per batch ---------------------------
// Cluster of 2 CTAs per batch (grid 128). CTA rank c owns k-slice and n-slice
// [c*128, c*128+128). Softmax over T fused in the prologue. Cross-CTA partial
// exchange via DSMEM stores + mbarrier release/acquire (no cluster.sync in the
// loop: it would flush L1D and evict the U matrices).
__global__ void __cluster_dims__(2,1,1) __launch_bounds__(512, 1)
k_scan(const int* __restrict__ input_len) {
    int bid  = blockIdx.x;
    int b    = bid >> 1;
    unsigned c    = ctarank();         // 0 or 1
    unsigned peer = c ^ 1u;
    int tid  = threadIdx.x;            // 512
    int w    = tid >> 5;               // 0..15 (k-sub within our 128-slice)
    int l    = tid & 31;               // 0..31 -> outputs n = 8l..8l+7

    __shared__ __align__(16) float red[16*H];      // partials [w][n]
    __shared__ __align__(16) float gs[T];
    __shared__ __align__(16) float h_own[128];
    __shared__ __align__(16) float rh_s[128];
    __shared__ __align__(16) float recv1[2][128];
    __shared__ __align__(16) float recv2[2][128];
    __shared__ __align__(8)  unsigned long long mbars[2];

    unsigned mb1 = smem_u32(&mbars[0]);
    unsigned mb2 = smem_u32(&mbars[1]);
    if (tid == 0) { mbar_init(mb1, 128); mbar_init(mb2, 128); }

    // ---- fused softmax over the batch's 512 scores (both CTAs identical) ----
    float av = g_att[b*T + tid];
    red[tid] = av;
    __syncthreads();
    for (int s = 256; s > 0; s >>= 1) {
        if (tid < s) red[tid] = fmaxf(red[tid], red[tid+s]);
        __syncthreads();
    }
    float mx = red[0];
    __syncthreads();
    float ex = expf(av - mx);
    red[tid] = ex;
    __syncthreads();
    for (int s = 256; s > 0; s >>= 1) {
        if (tid < s) red[tid] += red[tid+s];
        __syncthreads();
    }
    gs[tid] = ex / red[0];
    if (tid < 128) h_own[tid] = 0.0f;
    __syncthreads();

    // mbarriers + smem visible cluster-wide before any DSMEM traffic
    asm volatile("barrier.cluster.arrive.aligned;" ::: "memory");
    asm volatile("barrier.cluster.wait.aligned;"   ::: "memory");

    int len = input_len[b];
    // U pointers: global k-row = c*128 + 8w + kk, cols 8l..8l+7 (uint4 of 8 halves)
    const uint4* Ur4 = (const uint4*)(g_Urh + ((size_t)(c*128 + w*8))*H) + l;
    const uint4* Uh4 = (const uint4*)(g_Uhh + ((size_t)(c*128 + w*8))*H) + l;
    const int rs = H/8;                // uint4 per k row

    const bool in_red  = (tid < 256);
    const bool own     = in_red && ((unsigned)(tid >> 7) == c);
    const int  j       = tid & 127;    // local index within a 128-slice

    for (int t = 0; t < len; t++) {
        int par = t & 1;
        size_t row = (size_t)(b*T + t) * H;

        float pre_r = 0.f, pre_h = 0.f;
        if (own) { pre_r = g_preR[row + tid]; pre_h = g_preH[row + tid]; }

        // ---- matvec1 partials over our k-slice ----
        float a0=0.f,a1=0.f,a2=0.f,a3=0.f,a4=0.f,a5=0.f,a6=0.f,a7=0.f;
        #pragma unroll
        for (int kk = 0; kk < 8; kk++) {
            uint4 u = Ur4[kk * rs];
            const __half2* hu = (const __half2*)&u;
            float hv = h_own[w*8 + kk];
            float2 p0 = __half22float2(hu[0]);
            float2 p1 = __half22float2(hu[1]);
            float2 p2 = __half22float2(hu[2]);
            float2 p3 = __half22float2(hu[3]);
            a0 += hv*p0.x; a1 += hv*p0.y; a2 += hv*p1.x; a3 += hv*p1.y;
            a4 += hv*p2.x; a5 += hv*p2.y; a6 += hv*p3.x; a7 += hv*p3.y;
        }
        {
            float4* o = (float4*)(red + w*H + l*8);
            o[0] = make_float4(a0,a1,a2,a3);
            o[1] = make_float4(a4,a5,a6,a7);
        }
        __syncthreads();

        // ---- reduce + exchange + r gate ----
        if (in_red) {
            float ls = 0.f;
            #pragma unroll
            for (int p = 0; p < 16; p++) ls += red[p*H + tid];
            if (own) {
                mbar_wait_cluster(mb1, par);
                float tot = ls + recv1[par][j] + pre_r;
                float r = sigf(tot);
                rh_s[j] = r * h_own[j];
            } else {
                st_peer_f32(smem_u32(&recv1[par][j]), peer, ls);
                mbar_arrive_peer(mb1, peer);
            }
        }
        __syncthreads();

        // ---- matvec2 partials over rh ----
        a0=0.f;a1=0.f;a2=0.f;a3=0.f;a4=0.f;a5=0.f;a6=0.f;a7=0.f;
        #pragma unroll
        for (int kk = 0; kk < 8; kk++) {
            uint4 u = Uh4[kk * rs];
            const __half2* hu = (const __half2*)&u;
            float rv = rh_s[w*8 + kk];
            float2 p0 = __half22float2(hu[0]);
            float2 p1 = __half22float2(hu[1]);
            float2 p2 = __half22float2(hu[2]);
            float2 p3 = __half22float2(hu[3]);
            a0 += rv*p0.x; a1 += rv*p0.y; a2 += rv*p1.x; a3 += rv*p1.y;
            a4 += rv*p2.x; a5 += rv*p2.y; a6 += rv*p3.x; a7 += rv*p3.y;
        }
        {
            float4* o = (float4*)(red + w*H + l*8);
            o[0] = make_float4(a0,a1,a2,a3);
            o[1] = make_float4(a4,a5,a6,a7);
        }
        __syncthreads();

        // ---- reduce + exchange + candidate/blend ----
        if (in_red) {
            float ls = 0.f;
            #pragma unroll
            for (int p = 0; p < 16; p++) ls += red[p*H + tid];
            if (own) {
                mbar_wait_cluster(mb2, par);
                float s2 = ls + recv2[par][j] + pre_h;
                float hc = tanhf(s2);
                float gt = gs[t];
                float hn = gt * hc + (1.0f - gt) * h_own[j];
                g_eout[row + tid] = hn;
                h_own[j] = hn;
            } else {
                st_peer_f32(smem_u32(&recv2[par][j]), peer, ls);
                mbar_arrive_peer(mb2, peer);
            }
        }
        __syncthreads();
    }

    // both CTAs of a cluster run the same len; sync before exit
    asm volatile("barrier.cluster.arrive.aligned;" ::: "memory");
    asm volatile("barrier.cluster.wait.aligned;"   ::: "memory");
}

// ---------------- K6: span heads --------------------------------------------------
__global__ void k_heads(const int* __restrict__ input_len,
                        const float* __restrict__ Ws, const float* __restrict__ We,
                        float* __restrict__ out) {
    int row  = blockIdx.x * 8 + (threadIdx.x >> 5);   // 8 warps/block
    int lane = threadIdx.x & 31;
    int b = row >> 9, t = row & 511;
    int len = input_len[b];
    float qs = g_qs[b], qe = g_qe[b];
    float os, oe;
    if (t < len) {
        const float* e = g_eout + (size_t)row * H;
        float ds = 0.f, de = 0.f;
        #pragma unroll
        for (int k = lane; k < H; k += 32) {
            float ev = e[k];
            ds += ev * Ws[H + k];
            de += ev * We[H + k];
        }
        #pragma unroll
        for (int off = 16; off; off >>= 1) {
            ds += __shfl_xor_sync(0xFFFFFFFFu, ds, off);
            de += __shfl_xor_sync(0xFFFFFFFFu, de, off);
        }
        os = tanhf(qs + ds);
        oe = tanhf(qe + de);
    } else {
        os = tanhf(qs);
        oe = tanhf(qe);
    }
    if (lane == 0) {
        out[row]      = os;
        out[BT + row] = oe;
    }
}

// ---------------- launch ----------------------------------------------------------
extern "C" void kernel_launch(void* const* d_in, const int* in_sizes, int n_in,
                              void* d_out, int out_size) {
    const float* q   = (const float*)d_in[0];   // [B,H]
    const float* f   = (const float*)d_in[1];   // [B,T,H]
    const int*   len = (const int*)  d_in[2];   // [B]
    const float* W1  = (const float*)d_in[3];   // [7H,H]
    const float* b1  = (const float*)d_in[4];   // [H]
    const float* W2  = (const float*)d_in[5];   // [H,1]
    const float* b2  = (const float*)d_in[6];   // [1]
    const float* Wr  = (const float*)d_in[7];   // [H,H]
    const float* Ur  = (const float*)d_in[8];   // [H,H]
    const float* br  = (const float*)d_in[9];   // [H]
    const float* Wh  = (const float*)d_in[10];  // [H,H]
    const float* Uh  = (const float*)d_in[11];  // [H,H]
    const float* bh  = (const float*)d_in[12];  // [H]
    const float* Ws  = (const float*)d_in[13];  // [2H,1]
    const float* bs  = (const float*)d_in[14];  // [1]
    const float* We  = (const float*)d_in[15];  // [2H,1]
    const float* be  = (const float*)d_in[16];  // [1]
    float* out = (float*)d_out;                 // [2*B*T]

    // order chosen so the ncu-profiled slot (index 3) lands on k_scan
    k_prep<<<512, 512>>>(W1, Ur, Uh);
    k_att<<<BT/64, 256>>>(f, q, b1, W2, b2);
    k_pre<<<dim3(BT/64, 4), 256>>>(f, Wr, br, Wh, bh);
    k_scan<<<2*B, 512>>>(len);
    k_qsqe<<<1, B>>>(q, Ws, bs, We, be);
    k_heads<<<BT/8, 256>>>(len, Ws, We, out);
}